// round 4
// baseline (speedup 1.0000x reference)
#include <cuda_runtime.h>

#define NW      10
#define DIM     1024
#define THREADS 128

typedef unsigned long long ull;

// ---------- packed f32x2 helpers ----------
__device__ __forceinline__ ull pk(float lo, float hi) {
    ull r;
    asm("mov.b64 %0, {%1, %2};" : "=l"(r)
        : "r"(__float_as_uint(lo)), "r"(__float_as_uint(hi)));
    return r;
}
__device__ __forceinline__ void upk(ull v, float& lo, float& hi) {
    unsigned a, b;
    asm("mov.b64 {%0, %1}, %2;" : "=r"(a), "=r"(b) : "l"(v));
    lo = __uint_as_float(a); hi = __uint_as_float(b);
}
__device__ __forceinline__ ull swp(ull v) {
    float lo, hi; upk(v, lo, hi); return pk(hi, lo);
}
__device__ __forceinline__ ull fma2(ull a, ull b, ull c) {
    ull d;
    asm("fma.rn.f32x2 %0, %1, %2, %3;" : "=l"(d) : "l"(a), "l"(b), "l"(c));
    return d;
}
__device__ __forceinline__ ull mul2(ull a, ull b) {
    ull d;
    asm("mul.rn.f32x2 %0, %1, %2;" : "=l"(d) : "l"(a), "l"(b));
    return d;
}
__device__ __forceinline__ ull shfl64(ull v, int m) {
    float lo, hi; upk(v, lo, hi);
    lo = __shfl_xor_sync(0xffffffffu, lo, m);
    hi = __shfl_xor_sync(0xffffffffu, hi, m);
    return pk(lo, hi);
}

// ---------- gate coefficients (two pre-ordered variants per gate) ----------
// d_c1[j*32 ..]: complex gate, 16 ull:
//   [0..7]  std:     a2 ai2 b2 bi2 c2 ci2 d2 di2   (for lo lanes / reg gates)
//   [8..15] swapped: b2 bi2 a2 ai2 d2 di2 c2 ci2   (for hi lanes in swap-gates)
// d_c2[j*16 ..]: real RY gate, 8 ull:
//   [0..3] lo: {c2, ns2, s2, c2}   [4..7] hi: {ns2, c2, c2, s2}
__device__ float d_c1[NW * 32];
__device__ float d_c2[NW * 16];

__global__ void qsa_prep(const float* __restrict__ rx0,
                         const float* __restrict__ ry0,
                         const float* __restrict__ ry1) {
    int j = threadIdx.x;
    if (j < NW) {
        float cx, sx, cy, sy, cz, sz;
        sincosf(0.5f * rx0[j], &sx, &cx);
        sincosf(0.5f * ry0[j], &sy, &cy);
        sincosf(0.5f * ry1[j], &sz, &cz);
        // G = RY(ry0)@RX(rx0): a = cx*cy + i sx*sy ; b = -sy*cx - i sx*cy ;
        //                      c = sy*cx - i sx*cy ; d = cx*cy - i sx*sy
        float ar =  cx * cy, ai =  sx * sy;
        float br = -sy * cx, bi = -sx * cy;
        float cr =  sy * cx, ci = -sx * cy;
        float dr =  cx * cy, di = -sx * sy;
        float* g = d_c1 + j * 32;
        // std
        g[0]=ar;  g[1]=ar;   g[2]=-ai; g[3]=ai;
        g[4]=br;  g[5]=br;   g[6]=-bi; g[7]=bi;
        g[8]=cr;  g[9]=cr;   g[10]=-ci;g[11]=ci;
        g[12]=dr; g[13]=dr;  g[14]=-di;g[15]=di;
        // swapped (b,bi,a,ai,d,di,c,ci)
        g[16]=br; g[17]=br;  g[18]=-bi;g[19]=bi;
        g[20]=ar; g[21]=ar;  g[22]=-ai;g[23]=ai;
        g[24]=dr; g[25]=dr;  g[26]=-di;g[27]=di;
        g[28]=cr; g[29]=cr;  g[30]=-ci;g[31]=ci;
        float* h = d_c2 + j * 16;
        // lo: {c, -s, s, c}
        h[0]=cz;  h[1]=cz;   h[2]=-sz; h[3]=-sz;
        h[4]=sz;  h[5]=sz;   h[6]=cz;  h[7]=cz;
        // hi: {-s, c, c, s}
        h[8]=-sz; h[9]=-sz;  h[10]=cz; h[11]=cz;
        h[12]=cz; h[13]=cz;  h[14]=sz; h[15]=sz;
    }
}

// ---------- gates ----------
// Complex 2x2 on register bit kb (std coefficient order at g[0..7]).
__device__ __forceinline__ void cgate_reg(ull* r, const ull* g, const int kb) {
    const ull a2 = g[0], ai2 = g[1], b2 = g[2], bi2 = g[3];
    const ull c2 = g[4], ci2 = g[5], d2 = g[6], di2 = g[7];
#pragma unroll
    for (int m = 0; m < 8; m++) {
        if ((m >> kb) & 1) continue;
        const int m1 = m | (1 << kb);
        ull u = r[m], v = r[m1];
        ull us = swp(u), vs = swp(v);
        r[m]  = fma2(a2, u, fma2(ai2, us, fma2(b2, v, mul2(bi2, vs))));
        r[m1] = fma2(c2, u, fma2(ci2, us, fma2(d2, v, mul2(di2, vs))));
    }
}

// Complex swap-gate: applies the gate for the global bit hosted on lane bit lb,
// swapping that bit with reg bit kb (half shuffle traffic; layout is tracked
// by the caller). Only ONE ull per reg pair crosses the lane crossbar.
__device__ __forceinline__ void cgate_swap(ull* r, const ull* gbase,
                                           const int kb, const int lb, const int lane) {
    const bool hi = (lane >> lb) & 1;
    const ull* gv = gbase + (hi ? 8 : 0);
    const ull g0 = gv[0], g1 = gv[1], g2 = gv[2], g3 = gv[3];
    const ull g4 = gv[4], g5 = gv[5], g6 = gv[6], g7 = gv[7];
#pragma unroll
    for (int m = 0; m < 8; m++) {
        if ((m >> kb) & 1) continue;
        const int m1 = m | (1 << kb);
        ull send = hi ? r[m]  : r[m1];
        ull keep = hi ? r[m1] : r[m];
        ull recv = shfl64(send, 1 << lb);
        ull ks = swp(keep), rs = swp(recv);
        r[m]  = fma2(g0, keep, fma2(g1, ks, fma2(g2, recv, mul2(g3, rs))));
        r[m1] = fma2(g4, keep, fma2(g5, ks, fma2(g6, recv, mul2(g7, rs))));
    }
}

// Real RY on register bit kb (coeffs: c2=g[0], ns2=g[1], s2=g[2]).
__device__ __forceinline__ void rgate_reg(ull* r, const ull* g, const int kb) {
    const ull c2 = g[0], ns2 = g[1], s2 = g[2];
#pragma unroll
    for (int m = 0; m < 8; m++) {
        if ((m >> kb) & 1) continue;
        const int m1 = m | (1 << kb);
        ull u = r[m], v = r[m1];
        r[m]  = fma2(c2, u, mul2(ns2, v));
        r[m1] = fma2(c2, v, mul2(s2, u));
    }
}

// Real swap-gate on lane bit lb, swapping with reg bit kb.
__device__ __forceinline__ void rgate_swap(ull* r, const ull* gbase,
                                           const int kb, const int lb, const int lane) {
    const bool hi = (lane >> lb) & 1;
    const ull* gv = gbase + (hi ? 4 : 0);
    const ull g0 = gv[0], g1 = gv[1], g2 = gv[2], g3 = gv[3];
#pragma unroll
    for (int m = 0; m < 8; m++) {
        if ((m >> kb) & 1) continue;
        const int m1 = m | (1 << kb);
        ull send = hi ? r[m]  : r[m1];
        ull keep = hi ? r[m1] : r[m];
        ull recv = shfl64(send, 1 << lb);
        r[m]  = fma2(g0, keep, mul2(g1, recv));
        r[m1] = fma2(g2, keep, mul2(g3, recv));
    }
}

__global__ __launch_bounds__(THREADS)
void qsa_main(const float* __restrict__ x, float* __restrict__ out) {
    __shared__ ull   buf0[DIM];
    __shared__ ull   buf1[DIM];
    __shared__ ull   sgc1[NW * 16];   // 160
    __shared__ ull   sgc2[NW * 8];    // 80
    __shared__ float swred[4 * NW];
    __shared__ float s_inv2;

    const int t    = threadIdx.x;
    const int lane = t & 31;
    const int w    = t >> 5;
    const int row  = blockIdx.x;

    if (t < 128)              sgc1[t]       = ((const ull*)d_c1)[t];
    if (t < NW * 16 - 128)    sgc1[128 + t] = ((const ull*)d_c1)[128 + t];
    if (t < NW * 8)           sgc2[t]       = ((const ull*)d_c2)[t];

    // ---- Load (layout A: i = t + 128k; lane=bits0-4, warp=bits5-6, k=bits7-9) ----
    ull r[8];
    float ss = 0.f;
    const float* xr = x + (size_t)row * DIM;
#pragma unroll
    for (int k = 0; k < 8; k++) {
        float v = __ldg(xr + t + THREADS * k);
        r[k] = pk(v, 0.f);
        ss += v * v;
    }
#pragma unroll
    for (int o = 16; o; o >>= 1) ss += __shfl_xor_sync(0xffffffffu, ss, o);
    if (lane == 0) swred[w] = ss;
    __syncthreads();                                   // sync0 (covers sg preload)
    if (t == 0) {
        float s = swred[0] + swred[1] + swred[2] + swred[3];
        s_inv2 = 1.f / fmaxf(s, 1e-24f);               // == 1/max(norm,1e-12)^2
    }

    // ======== Layer 1 (fused complex RY*RX per wire) ========
    cgate_reg(r, sgc1 + 16 * 0, 2);         // q0 <-> bit9
    cgate_reg(r, sgc1 + 16 * 1, 1);         // q1 <-> bit8
    cgate_reg(r, sgc1 + 16 * 2, 0);         // q2 <-> bit7
    cgate_swap(r, sgc1 + 16 * 5, 2, 4, lane);  // q5 (bit4) : reg2<->lane4
    cgate_swap(r, sgc1 + 16 * 6, 1, 3, lane);  // q6 (bit3) : reg1<->lane3
    cgate_swap(r, sgc1 + 16 * 7, 0, 2, lane);  // q7 (bit2) : reg0<->lane2
    cgate_swap(r, sgc1 + 16 * 8, 2, 1, lane);  // q8 (bit1) : reg2<->lane1
    cgate_swap(r, sgc1 + 16 * 9, 1, 0, lane);  // q9 (bit0) : reg1<->lane0
    // Tracked layout A': lane0..4 -> global bits {3,4,7,8,9}; w -> {5,6};
    //                    reg k0 -> bit2, k1 -> bit0, k2 -> bit1.

    // ---- Exchange A' -> B with XOR swizzle sigma(i) = i ^ ((i>>7)&7) ----
    // (conflict-free scatter: sigma low-5 has full rank on the lane-varying bits)
    {
        const int base = ((lane & 1) << 3) | (((lane >> 1) & 1) << 4)
                       | (((lane >> 2) & 1) << 7) | (((lane >> 3) & 1) << 8)
                       | (((lane >> 4) & 1) << 9) | (w << 5);
        const int xv = (lane >> 2) & 7;    // == (i>>7)&7, constant per thread
#pragma unroll
        for (int k = 0; k < 8; k++) {
            const int kmap = ((k & 1) << 2) | ((k >> 1) & 1) | (((k >> 2) & 1) << 1);
            buf0[base | (kmap ^ xv)] = r[k];
        }
    }
    __syncthreads();                                   // sync1
#pragma unroll
    for (int k = 0; k < 8; k++) {
        const int rx = ((k >> 2) & 1) | (w << 1);      // == (j>>7)&7 for j=lane|k<<5|w<<8
        r[k] = buf0[(lane ^ rx) | (k << 5) | (w << 8)];
    }
    // Layout B: lane -> bits0-4, k -> bits5-7, w -> bits8-9.

    cgate_reg(r, sgc1 + 16 * 4, 0);         // q4 <-> bit5
    cgate_reg(r, sgc1 + 16 * 3, 1);         // q3 <-> bit6

    // ---- CNOT ring (fixed suffix-XOR permutation), fused with exchange B -> A ----
#pragma unroll
    for (int k = 0; k < 8; k++) {
        unsigned i = (unsigned)(lane | (k << 5) | (w << 8));
        unsigned y = i;
        y ^= y >> 1; y ^= y >> 2; y ^= y >> 4; y ^= y >> 8;
        unsigned dst = (y & 0x1FFu) | (((y ^ (i >> 9)) & 1u) << 9);
        buf1[dst] = r[k];
    }
    __syncthreads();                                   // sync2
#pragma unroll
    for (int k = 0; k < 8; k++) r[k] = buf1[t + THREADS * k];
    // Layout A again.

    // ======== Layer 2 (real RY per wire) ========
    rgate_reg(r, sgc2 + 8 * 0, 2);          // q0
    rgate_reg(r, sgc2 + 8 * 1, 1);          // q1
    rgate_reg(r, sgc2 + 8 * 2, 0);          // q2
    rgate_swap(r, sgc2 + 8 * 5, 2, 4, lane);   // q5
    rgate_swap(r, sgc2 + 8 * 6, 1, 3, lane);   // q6
    rgate_swap(r, sgc2 + 8 * 7, 0, 2, lane);   // q7
    rgate_swap(r, sgc2 + 8 * 8, 2, 1, lane);   // q8
    rgate_swap(r, sgc2 + 8 * 9, 1, 0, lane);   // q9
    // Layout A' again (same swap sequence).

    // ---- Exchange A' -> B (same sigma swizzle) ----
    {
        const int base = ((lane & 1) << 3) | (((lane >> 1) & 1) << 4)
                       | (((lane >> 2) & 1) << 7) | (((lane >> 3) & 1) << 8)
                       | (((lane >> 4) & 1) << 9) | (w << 5);
        const int xv = (lane >> 2) & 7;
#pragma unroll
        for (int k = 0; k < 8; k++) {
            const int kmap = ((k & 1) << 2) | ((k >> 1) & 1) | (((k >> 2) & 1) << 1);
            buf0[base | (kmap ^ xv)] = r[k];
        }
    }
    __syncthreads();                                   // sync3
#pragma unroll
    for (int k = 0; k < 8; k++) {
        const int rx = ((k >> 2) & 1) | (w << 1);
        r[k] = buf0[(lane ^ rx) | (k << 5) | (w << 8)];
    }
    // Layout B.

    rgate_reg(r, sgc2 + 8 * 4, 0);          // q4 <-> bit5
    rgate_reg(r, sgc2 + 8 * 3, 1);          // q3 <-> bit6

    // ======== <Z_j> reduction (layout B: bits5-7 = k; 8,9 = w; 0-4 = lane) ====
    float tot = 0.f, a2 = 0.f, a3 = 0.f, a4 = 0.f;
#pragma unroll
    for (int k = 0; k < 8; k++) {
        float px, py; upk(r[k], px, py);
        float p = px * px + py * py;
        tot += p;
        a4 += (k & 1) ? -p : p;   // q4 <-> bit5
        a3 += (k & 2) ? -p : p;   // q3 <-> bit6
        a2 += (k & 4) ? -p : p;   // q2 <-> bit7
    }
    // Spawning sum/difference tree over lane bits.
    float s = tot, d4, d3, d2v, d1, d0;
    {
        float n = __shfl_xor_sync(0xffffffffu, s, 16);
        d4 = (lane & 16) ? n - s : s - n; s += n;
    }
    {
        float n = __shfl_xor_sync(0xffffffffu, s, 8);
        d3 = (lane & 8) ? n - s : s - n; s += n;
        d4 += __shfl_xor_sync(0xffffffffu, d4, 8);
    }
    {
        float n = __shfl_xor_sync(0xffffffffu, s, 4);
        d2v = (lane & 4) ? n - s : s - n; s += n;
        d4 += __shfl_xor_sync(0xffffffffu, d4, 4);
        d3 += __shfl_xor_sync(0xffffffffu, d3, 4);
    }
    {
        float n = __shfl_xor_sync(0xffffffffu, s, 2);
        d1 = (lane & 2) ? n - s : s - n; s += n;
        d4 += __shfl_xor_sync(0xffffffffu, d4, 2);
        d3 += __shfl_xor_sync(0xffffffffu, d3, 2);
        d2v += __shfl_xor_sync(0xffffffffu, d2v, 2);
    }
    {
        float n = __shfl_xor_sync(0xffffffffu, s, 1);
        d0 = (lane & 1) ? n - s : s - n; s += n;
        d4 += __shfl_xor_sync(0xffffffffu, d4, 1);
        d3 += __shfl_xor_sync(0xffffffffu, d3, 1);
        d2v += __shfl_xor_sync(0xffffffffu, d2v, 1);
        d1 += __shfl_xor_sync(0xffffffffu, d1, 1);
    }
#pragma unroll
    for (int o = 16; o; o >>= 1) {
        a2 += __shfl_xor_sync(0xffffffffu, a2, o);
        a3 += __shfl_xor_sync(0xffffffffu, a3, o);
        a4 += __shfl_xor_sync(0xffffffffu, a4, o);
    }
    if (lane == 0) {
        swred[w * NW + 0] = ((w >> 1) & 1) ? -s : s;   // q0 <-> bit9 (w bit1)
        swred[w * NW + 1] = ( w       & 1) ? -s : s;   // q1 <-> bit8
        swred[w * NW + 2] = a2;
        swred[w * NW + 3] = a3;
        swred[w * NW + 4] = a4;
        swred[w * NW + 5] = d4;
        swred[w * NW + 6] = d3;
        swred[w * NW + 7] = d2v;
        swred[w * NW + 8] = d1;
        swred[w * NW + 9] = d0;
    }
    __syncthreads();                                   // sync4
    if (t < NW) {
        float e = swred[t] + swred[NW + t] + swred[2 * NW + t] + swred[3 * NW + t];
        out[(size_t)row * NW + t] = e * s_inv2;
    }
}

extern "C" void kernel_launch(void* const* d_in, const int* in_sizes, int n_in,
                              void* d_out, int out_size) {
    const float* x   = (const float*)d_in[0];
    const float* rx0 = (const float*)d_in[1];
    const float* ry0 = (const float*)d_in[2];
    const float* ry1 = (const float*)d_in[3];
    float* out = (float*)d_out;

    int nrows = in_sizes[0] / DIM;  // 4096

    qsa_prep<<<1, 32>>>(rx0, ry0, ry1);
    qsa_main<<<nrows, THREADS>>>(x, out);
}

// round 5
// speedup vs baseline: 1.1135x; 1.1135x over previous
#include <cuda_runtime.h>

#define NW      10
#define DIM     1024
#define THREADS 128

typedef unsigned long long ull;

// ---------- packed f32x2 helpers ----------
__device__ __forceinline__ ull pk(float lo, float hi) {
    ull r;
    asm("mov.b64 %0, {%1, %2};" : "=l"(r)
        : "r"(__float_as_uint(lo)), "r"(__float_as_uint(hi)));
    return r;
}
__device__ __forceinline__ void upk(ull v, float& lo, float& hi) {
    unsigned a, b;
    asm("mov.b64 {%0, %1}, %2;" : "=r"(a), "=r"(b) : "l"(v));
    lo = __uint_as_float(a); hi = __uint_as_float(b);
}
__device__ __forceinline__ ull swp(ull v) {
    float lo, hi; upk(v, lo, hi); return pk(hi, lo);
}
__device__ __forceinline__ ull fma2(ull a, ull b, ull c) {
    ull d;
    asm("fma.rn.f32x2 %0, %1, %2, %3;" : "=l"(d) : "l"(a), "l"(b), "l"(c));
    return d;
}
__device__ __forceinline__ ull mul2(ull a, ull b) {
    ull d;
    asm("mul.rn.f32x2 %0, %1, %2;" : "=l"(d) : "l"(a), "l"(b));
    return d;
}

// ---------- gate coefficients ----------
// staging in global (prep kernel writes), then D2D-copied into __constant__
// so gate loads use the constant port (LDC) instead of the smem/LSU crossbar.
__device__    ull d_g1[NW * 8];   // complex fused RY*RX: a2 ai2 b2 bi2 c2 ci2 d2 di2
__device__    ull d_g2[NW * 4];   // real RY: c2 s2 ns2 (pad)
__constant__  ull c_g1[NW * 8];
__constant__  ull c_g2[NW * 4];

__global__ void qsa_prep(const float* __restrict__ rx0,
                         const float* __restrict__ ry0,
                         const float* __restrict__ ry1) {
    int j = threadIdx.x;
    if (j < NW) {
        float cx, sx, cy, sy, cz, sz;
        sincosf(0.5f * rx0[j], &sx, &cx);
        sincosf(0.5f * ry0[j], &sy, &cy);
        sincosf(0.5f * ry1[j], &sz, &cz);
        // G = RY(ry0)@RX(rx0): a = cx*cy + i sx*sy ; b = -sy*cx - i sx*cy ;
        //                      c = sy*cx - i sx*cy ; d = cx*cy - i sx*sy
        float ar =  cx * cy, ai =  sx * sy;
        float br = -sy * cx, bi = -sx * cy;
        float cr =  sy * cx, ci = -sx * cy;
        float dr =  cx * cy, di = -sx * sy;
        ull* g = d_g1 + j * 8;
        g[0] = pk(ar, ar);   g[1] = pk(-ai, ai);
        g[2] = pk(br, br);   g[3] = pk(-bi, bi);
        g[4] = pk(cr, cr);   g[5] = pk(-ci, ci);
        g[6] = pk(dr, dr);   g[7] = pk(-di, di);
        ull* h = d_g2 + j * 4;
        h[0] = pk(cz, cz);   h[1] = pk(sz, sz);   h[2] = pk(-sz, -sz);
        h[3] = 0;
    }
}

// ---------- gates (coefficients from __constant__) ----------
// Complex 2x2 on register bit kb.
__device__ __forceinline__ void cgate_reg(ull* r, const int gi, const int kb) {
    const ull a2 = c_g1[gi+0], ai2 = c_g1[gi+1], b2 = c_g1[gi+2], bi2 = c_g1[gi+3];
    const ull c2 = c_g1[gi+4], ci2 = c_g1[gi+5], d2 = c_g1[gi+6], di2 = c_g1[gi+7];
#pragma unroll
    for (int m = 0; m < 8; m++) {
        if ((m >> kb) & 1) continue;
        const int m1 = m | (1 << kb);
        ull u = r[m], v = r[m1];
        ull us = swp(u), vs = swp(v);
        r[m]  = fma2(a2, u, fma2(ai2, us, fma2(b2, v, mul2(bi2, vs))));
        r[m1] = fma2(c2, u, fma2(ci2, us, fma2(d2, v, mul2(di2, vs))));
    }
}

// Complex 2x2 on lane bit lb via shuffle (coeff role select hoisted per gate).
__device__ __forceinline__ void cgate_shfl(ull* r, const int gi,
                                           const int lb, const int lane) {
    const bool hi = (lane >> lb) & 1;
    const ull p2  = hi ? c_g1[gi+6] : c_g1[gi+0];
    const ull pi2 = hi ? c_g1[gi+7] : c_g1[gi+1];
    const ull q2  = hi ? c_g1[gi+4] : c_g1[gi+2];
    const ull qi2 = hi ? c_g1[gi+5] : c_g1[gi+3];
#pragma unroll
    for (int k = 0; k < 8; k++) {
        float ux, uy; upk(r[k], ux, uy);
        float vx = __shfl_xor_sync(0xffffffffu, ux, 1 << lb);
        float vy = __shfl_xor_sync(0xffffffffu, uy, 1 << lb);
        r[k] = fma2(p2, r[k],
               fma2(pi2, pk(uy, ux),
               fma2(q2, pk(vx, vy), mul2(qi2, pk(vy, vx)))));
    }
}

// Real RY on register bit kb.
__device__ __forceinline__ void rgate_reg(ull* r, const int gi, const int kb) {
    const ull c2 = c_g2[gi+0], s2 = c_g2[gi+1], ns2 = c_g2[gi+2];
#pragma unroll
    for (int m = 0; m < 8; m++) {
        if ((m >> kb) & 1) continue;
        const int m1 = m | (1 << kb);
        ull u = r[m], v = r[m1];
        r[m]  = fma2(c2, u, mul2(ns2, v));
        r[m1] = fma2(c2, v, mul2(s2, u));
    }
}

// Real RY on lane bit lb via shuffle.
__device__ __forceinline__ void rgate_shfl(ull* r, const int gi,
                                           const int lb, const int lane) {
    const bool hi = (lane >> lb) & 1;
    const ull c2 = c_g2[gi+0];
    const ull q2 = hi ? c_g2[gi+1] : c_g2[gi+2];   // +s / -s
#pragma unroll
    for (int k = 0; k < 8; k++) {
        float ux, uy; upk(r[k], ux, uy);
        float vx = __shfl_xor_sync(0xffffffffu, ux, 1 << lb);
        float vy = __shfl_xor_sync(0xffffffffu, uy, 1 << lb);
        r[k] = fma2(c2, r[k], mul2(q2, pk(vx, vy)));
    }
}

__global__ __launch_bounds__(THREADS)
void qsa_main(const float* __restrict__ x, float* __restrict__ out,
              const int nrows) {
    __shared__ ull   buf0[DIM];
    __shared__ ull   buf1[DIM];
    __shared__ float snorm[2][4];     // parity double-buffered per row iter
    __shared__ float swred[4 * NW];

    const int t    = threadIdx.x;
    const int lane = t & 31;
    const int w    = t >> 5;

    int par = 0;
    for (int row = blockIdx.x; row < nrows; row += gridDim.x, par ^= 1) {
        // ---- Load (layout A: i = t + 128k; lane=bits0-4, warp=bits5-6, k=bits7-9)
        ull r[8];
        float ss = 0.f;
        const float* xr = x + (size_t)row * DIM;
#pragma unroll
        for (int k = 0; k < 8; k++) {
            float v = __ldg(xr + t + THREADS * k);
            r[k] = pk(v, 0.f);
            ss += v * v;
        }
#pragma unroll
        for (int o = 16; o; o >>= 1) ss += __shfl_xor_sync(0xffffffffu, ss, o);
        if (lane == 0) snorm[par][w] = ss;   // consumed by output threads post-sync4

        // ======== Layer 1 (fused complex RY*RX per wire) ========
        cgate_reg(r, 8 * 0, 2);          // q0 <-> bit9
        cgate_reg(r, 8 * 1, 1);          // q1 <-> bit8
        cgate_reg(r, 8 * 2, 0);          // q2 <-> bit7
        cgate_shfl(r, 8 * 5, 4, lane);   // q5 <-> bit4
        cgate_shfl(r, 8 * 6, 3, lane);   // q6
        cgate_shfl(r, 8 * 7, 2, lane);   // q7
        cgate_shfl(r, 8 * 8, 1, lane);   // q8
        cgate_shfl(r, 8 * 9, 0, lane);   // q9 <-> bit0

        // ---- Exchange A -> B (layout B: i = lane | (k<<5) | (w<<8)) ----
#pragma unroll
        for (int k = 0; k < 8; k++) buf0[t + THREADS * k] = r[k];
        __syncthreads();                                   // sync1
#pragma unroll
        for (int k = 0; k < 8; k++) r[k] = buf0[lane | (k << 5) | (w << 8)];

        cgate_reg(r, 8 * 4, 0);          // q4 <-> bit5
        cgate_reg(r, 8 * 3, 1);          // q3 <-> bit6

        // ---- CNOT ring (suffix-XOR permutation), fused with exchange B -> A ----
#pragma unroll
        for (int k = 0; k < 8; k++) {
            unsigned i = (unsigned)(lane | (k << 5) | (w << 8));
            unsigned y = i;
            y ^= y >> 1; y ^= y >> 2; y ^= y >> 4; y ^= y >> 8;
            unsigned dst = (y & 0x1FFu) | (((y ^ (i >> 9)) & 1u) << 9);
            buf1[dst] = r[k];
        }
        __syncthreads();                                   // sync2
#pragma unroll
        for (int k = 0; k < 8; k++) r[k] = buf1[t + THREADS * k];

        // ======== Layer 2 (real RY per wire) ========
        rgate_reg(r, 4 * 0, 2);
        rgate_reg(r, 4 * 1, 1);
        rgate_reg(r, 4 * 2, 0);
        rgate_shfl(r, 4 * 5, 4, lane);
        rgate_shfl(r, 4 * 6, 3, lane);
        rgate_shfl(r, 4 * 7, 2, lane);
        rgate_shfl(r, 4 * 8, 1, lane);
        rgate_shfl(r, 4 * 9, 0, lane);

        // ---- Exchange A -> B again ----
#pragma unroll
        for (int k = 0; k < 8; k++) buf0[t + THREADS * k] = r[k];
        __syncthreads();                                   // sync3
#pragma unroll
        for (int k = 0; k < 8; k++) r[k] = buf0[lane | (k << 5) | (w << 8)];

        rgate_reg(r, 4 * 4, 0);          // q4 <-> bit5
        rgate_reg(r, 4 * 3, 1);          // q3 <-> bit6

        // ======== <Z_j> reduction (layout B: bits5-7 = k; 8,9 = w; 0-4 = lane) ====
        float tot = 0.f, a2 = 0.f, a3 = 0.f, a4 = 0.f;
#pragma unroll
        for (int k = 0; k < 8; k++) {
            float px, py; upk(r[k], px, py);
            float p = px * px + py * py;
            tot += p;
            a4 += (k & 1) ? -p : p;   // q4 <-> bit5
            a3 += (k & 2) ? -p : p;   // q3 <-> bit6
            a2 += (k & 4) ? -p : p;   // q2 <-> bit7
        }
        // Spawning sum/difference tree over lane bits.
        float s = tot, d4, d3, d2v, d1, d0;
        {
            float n = __shfl_xor_sync(0xffffffffu, s, 16);
            d4 = (lane & 16) ? n - s : s - n; s += n;
        }
        {
            float n = __shfl_xor_sync(0xffffffffu, s, 8);
            d3 = (lane & 8) ? n - s : s - n; s += n;
            d4 += __shfl_xor_sync(0xffffffffu, d4, 8);
        }
        {
            float n = __shfl_xor_sync(0xffffffffu, s, 4);
            d2v = (lane & 4) ? n - s : s - n; s += n;
            d4 += __shfl_xor_sync(0xffffffffu, d4, 4);
            d3 += __shfl_xor_sync(0xffffffffu, d3, 4);
        }
        {
            float n = __shfl_xor_sync(0xffffffffu, s, 2);
            d1 = (lane & 2) ? n - s : s - n; s += n;
            d4 += __shfl_xor_sync(0xffffffffu, d4, 2);
            d3 += __shfl_xor_sync(0xffffffffu, d3, 2);
            d2v += __shfl_xor_sync(0xffffffffu, d2v, 2);
        }
        {
            float n = __shfl_xor_sync(0xffffffffu, s, 1);
            d0 = (lane & 1) ? n - s : s - n; s += n;
            d4 += __shfl_xor_sync(0xffffffffu, d4, 1);
            d3 += __shfl_xor_sync(0xffffffffu, d3, 1);
            d2v += __shfl_xor_sync(0xffffffffu, d2v, 1);
            d1 += __shfl_xor_sync(0xffffffffu, d1, 1);
        }
#pragma unroll
        for (int o = 16; o; o >>= 1) {
            a2 += __shfl_xor_sync(0xffffffffu, a2, o);
            a3 += __shfl_xor_sync(0xffffffffu, a3, o);
            a4 += __shfl_xor_sync(0xffffffffu, a4, o);
        }
        if (lane == 0) {
            swred[w * NW + 0] = ((w >> 1) & 1) ? -s : s;   // q0 <-> bit9 (w bit1)
            swred[w * NW + 1] = ( w       & 1) ? -s : s;   // q1 <-> bit8
            swred[w * NW + 2] = a2;
            swred[w * NW + 3] = a3;
            swred[w * NW + 4] = a4;
            swred[w * NW + 5] = d4;
            swred[w * NW + 6] = d3;
            swred[w * NW + 7] = d2v;
            swred[w * NW + 8] = d1;
            swred[w * NW + 9] = d0;
        }
        __syncthreads();                                   // sync4
        if (t < NW) {
            float sn = snorm[par][0] + snorm[par][1] + snorm[par][2] + snorm[par][3];
            float e  = swred[t] + swred[NW + t] + swred[2 * NW + t] + swred[3 * NW + t];
            out[(size_t)row * NW + t] = e / fmaxf(sn, 1e-24f);
        }
        // next iteration's snorm writes go to snorm[par^1]; swred rewrites are
        // ordered behind sync3 of the next row (which requires these reads done).
    }
}

extern "C" void kernel_launch(void* const* d_in, const int* in_sizes, int n_in,
                              void* d_out, int out_size) {
    const float* x   = (const float*)d_in[0];
    const float* rx0 = (const float*)d_in[1];
    const float* ry0 = (const float*)d_in[2];
    const float* ry1 = (const float*)d_in[3];
    float* out = (float*)d_out;

    int nrows = in_sizes[0] / DIM;  // 4096

    qsa_prep<<<1, 32>>>(rx0, ry0, ry1);

    // Stage gate coeffs into __constant__ (D2D async copy — graph-capturable).
    void *p1 = nullptr, *p2 = nullptr;
    cudaGetSymbolAddress(&p1, d_g1);
    cudaGetSymbolAddress(&p2, d_g2);
    cudaMemcpyToSymbolAsync(c_g1, p1, sizeof(ull) * NW * 8, 0,
                            cudaMemcpyDeviceToDevice, 0);
    cudaMemcpyToSymbolAsync(c_g2, p2, sizeof(ull) * NW * 4, 0,
                            cudaMemcpyDeviceToDevice, 0);

    // Persistent CTAs: single wave (7 CTAs/SM x 148 SMs), rows strided.
    int grid = 1036;
    if (grid > nrows) grid = nrows;
    qsa_main<<<grid, THREADS>>>(x, out, nrows);
}